// round 7
// baseline (speedup 1.0000x reference)
#include <cuda_runtime.h>
#include <cuda_bf16.h>
#include <cstdint>
#include <math.h>

// Problem constants
#define N2     8192     // 2N rows
#define HALF_N 4096     // pos index = i ^ HALF_N
#define D      512      // feature dim
#define SCALE  2.0f     // 1 / TEMPERATURE

// Tiling
#define TM     128
#define TN     128
#define KC     64       // bf16 per k-chunk (128 bytes/row)
#define NCHUNK (D / KC) // 8
#define NJT    (N2 / TN)
#define STAGE_BYTES (TM * KC * 2 * 2)      // A+B one stage = 32 KB
#define SMEM_BYTES  (2 * STAGE_BYTES)      // 2 stages = 64 KB

// Device scratch (static: allocation-free per harness rules)
__device__ __nv_bfloat16 g_zb[N2 * D];   // normalized rows, bf16 (8 MB)
__device__ float g_partS[NJT * N2];      // partial exp-sums per (jtile,row)
__device__ float g_pos[N2];              // positive logit per row
__device__ float g_lsep[N2];             // lse - pos per row

// ---------------------------------------------------------------------------
// PTX helpers
// ---------------------------------------------------------------------------
__device__ __forceinline__ uint32_t smem_u32(const void* p) {
    uint32_t a;
    asm("{ .reg .u64 t; cvta.to.shared.u64 t, %1; cvt.u32.u64 %0, t; }"
        : "=r"(a) : "l"(p));
    return a;
}
__device__ __forceinline__ void cp_async16(uint32_t dst, const void* src) {
    asm volatile("cp.async.cg.shared.global [%0], [%1], 16;"
                 :: "r"(dst), "l"(src) : "memory");
}
__device__ __forceinline__ void cp_commit() {
    asm volatile("cp.async.commit_group;" ::: "memory");
}
template <int N>
__device__ __forceinline__ void cp_wait() {
    asm volatile("cp.async.wait_group %0;" :: "n"(N) : "memory");
}
__device__ __forceinline__ void ldm_x4(uint32_t& r0, uint32_t& r1, uint32_t& r2,
                                       uint32_t& r3, uint32_t addr) {
    asm volatile("ldmatrix.sync.aligned.m8n8.x4.shared.b16 {%0,%1,%2,%3}, [%4];"
                 : "=r"(r0), "=r"(r1), "=r"(r2), "=r"(r3) : "r"(addr));
}
__device__ __forceinline__ void mma16816(float* d, const uint32_t* a,
                                         uint32_t b0, uint32_t b1) {
    asm volatile(
        "mma.sync.aligned.m16n8k16.row.col.f32.bf16.bf16.f32 "
        "{%0,%1,%2,%3}, {%4,%5,%6,%7}, {%8,%9}, {%0,%1,%2,%3};"
        : "+f"(d[0]), "+f"(d[1]), "+f"(d[2]), "+f"(d[3])
        : "r"(a[0]), "r"(a[1]), "r"(a[2]), "r"(a[3]), "r"(b0), "r"(b1));
}

// swizzled byte offset inside a 128x64-bf16 tile (128 B rows, 16 B units)
__device__ __forceinline__ uint32_t sw_off(int row, int unit) {
    return (uint32_t)(row * 128 + ((unit ^ (row & 7)) << 4));
}

// ---------------------------------------------------------------------------
// Kernel 1: row L2-normalize + bf16 convert. One block (128 thr) per row.
// ---------------------------------------------------------------------------
__global__ void __launch_bounds__(128) normalize_kernel(const float* __restrict__ z) {
    int row = blockIdx.x;
    int t   = threadIdx.x;
    float4 v = ((const float4*)(z + (size_t)row * D))[t];
    float ss = v.x * v.x + v.y * v.y + v.z * v.z + v.w * v.w;
    #pragma unroll
    for (int off = 16; off > 0; off >>= 1)
        ss += __shfl_xor_sync(0xffffffffu, ss, off);
    __shared__ float ws[4];
    if ((t & 31) == 0) ws[t >> 5] = ss;
    __syncthreads();
    float inv = 1.0f / fmaxf(sqrtf(ws[0] + ws[1] + ws[2] + ws[3]), 1e-12f);
    __nv_bfloat162 p0 = __floats2bfloat162_rn(v.x * inv, v.y * inv);
    __nv_bfloat162 p1 = __floats2bfloat162_rn(v.z * inv, v.w * inv);
    uint2 o;
    o.x = *(const uint32_t*)&p0;
    o.y = *(const uint32_t*)&p1;
    ((uint2*)(g_zb + (size_t)row * D))[t] = o;
}

// ---------------------------------------------------------------------------
// Kernel 2: 128x128 sim tile via mma.sync bf16 + exp-sum epilogue.
// Grid (64,64); 256 threads = 8 warps, warp tile 64x32 (wm 0..1, wn 0..3).
// ---------------------------------------------------------------------------
__global__ void __launch_bounds__(256, 2) sim_kernel() {
    extern __shared__ __align__(128) char smem[];
    __shared__ float red[4][TM];         // cross-warp (wn) reduction

    const int tid = threadIdx.x;
    const int wid = tid >> 5;
    const int lid = tid & 31;
    const int wm  = wid & 1;             // 0..1 -> 64 rows
    const int wn  = wid >> 1;            // 0..3 -> 32 cols
    const int i0  = blockIdx.x * TM;
    const int j0  = blockIdx.y * TN;

    const uint32_t sA0 = smem_u32(smem);                 // stage0 A
    // stage layout: [stage][A 16KB | B 16KB]
    auto a_base = [&](int s) { return sA0 + (uint32_t)s * STAGE_BYTES; };
    auto b_base = [&](int s) { return sA0 + (uint32_t)s * STAGE_BYTES + TM * KC * 2; };

    // ---- load helper: stage chunk c into buffer s ----
    auto load_chunk = [&](int c, int s) {
        const uint32_t ab = a_base(s), bb = b_base(s);
        #pragma unroll
        for (int u = 0; u < 4; u++) {                    // 1024 units / 256 thr
            int unit = tid + u * 256;
            int r = unit >> 3, b = unit & 7;
            uint32_t off = sw_off(r, b);
            const __nv_bfloat16* src_a = g_zb + (size_t)(i0 + r) * D + c * KC + b * 8;
            const __nv_bfloat16* src_b = g_zb + (size_t)(j0 + r) * D + c * KC + b * 8;
            cp_async16(ab + off, src_a);
            cp_async16(bb + off, src_b);
        }
        cp_commit();
    };

    float acc[4][4][4];
    #pragma unroll
    for (int mm = 0; mm < 4; mm++)
        #pragma unroll
        for (int nn = 0; nn < 4; nn++)
            #pragma unroll
            for (int e = 0; e < 4; e++) acc[mm][nn][e] = 0.0f;

    load_chunk(0, 0);

    for (int c = 0; c < NCHUNK; c++) {
        if (c + 1 < NCHUNK) {
            load_chunk(c + 1, (c + 1) & 1);
            cp_wait<1>();
        } else {
            cp_wait<0>();
        }
        __syncthreads();

        const uint32_t ab = a_base(c & 1), bb = b_base(c & 1);
        const int tile_id = lid >> 3, rowin = lid & 7;

        #pragma unroll
        for (int ks = 0; ks < 4; ks++) {                 // k0 = ks*16
            const int cu = ks * 2 + (tile_id >> 1);      // 16B unit for this lane
            uint32_t a[4][4], bfr[2][4];
            #pragma unroll
            for (int mm = 0; mm < 4; mm++) {
                int m = wm * 64 + mm * 16 + rowin + (tile_id & 1) * 8;
                ldm_x4(a[mm][0], a[mm][1], a[mm][2], a[mm][3],
                       ab + sw_off(m, cu));
            }
            #pragma unroll
            for (int nb = 0; nb < 2; nb++) {
                int n = wn * 32 + nb * 16 + rowin + (tile_id & 1) * 8;
                ldm_x4(bfr[nb][0], bfr[nb][1], bfr[nb][2], bfr[nb][3],
                       bb + sw_off(n, cu));
            }
            #pragma unroll
            for (int mm = 0; mm < 4; mm++) {
                #pragma unroll
                for (int nn = 0; nn < 4; nn++) {
                    int nb = nn >> 1, odd = nn & 1;
                    mma16816(acc[mm][nn], a[mm],
                             bfr[nb][odd], bfr[nb][2 + odd]);
                }
            }
        }
        __syncthreads();
    }

    // ---- Epilogue: scale, skip diagonal, capture positive, exp-sum ----
    const int gq = lid >> 2;          // accumulator row group 0..7
    const int qi = lid & 3;           // col pair 0..3
    #pragma unroll
    for (int mm = 0; mm < 4; mm++) {
        float rs0 = 0.0f, rs1 = 0.0f;
        const int gi0 = i0 + wm * 64 + mm * 16 + gq;
        const int gi1 = gi0 + 8;
        const int p0  = gi0 ^ HALF_N;
        const int p1  = gi1 ^ HALF_N;
        #pragma unroll
        for (int nn = 0; nn < 4; nn++) {
            const int j = j0 + wn * 32 + nn * 8 + qi * 2;
            float l00 = SCALE * acc[mm][nn][0];
            float l01 = SCALE * acc[mm][nn][1];
            float l10 = SCALE * acc[mm][nn][2];
            float l11 = SCALE * acc[mm][nn][3];
            if (j     == p0)  g_pos[gi0] = l00;
            if (j + 1 == p0)  g_pos[gi0] = l01;
            if (j     == p1)  g_pos[gi1] = l10;
            if (j + 1 == p1)  g_pos[gi1] = l11;
            if (j     != gi0) rs0 += __expf(l00);
            if (j + 1 != gi0) rs0 += __expf(l01);
            if (j     != gi1) rs1 += __expf(l10);
            if (j + 1 != gi1) rs1 += __expf(l11);
        }
        // reduce across the 4 lanes sharing a row (qi dimension)
        rs0 += __shfl_xor_sync(0xffffffffu, rs0, 1);
        rs0 += __shfl_xor_sync(0xffffffffu, rs0, 2);
        rs1 += __shfl_xor_sync(0xffffffffu, rs1, 1);
        rs1 += __shfl_xor_sync(0xffffffffu, rs1, 2);
        if (qi == 0) {
            red[wn][wm * 64 + mm * 16 + gq]     = rs0;
            red[wn][wm * 64 + mm * 16 + gq + 8] = rs1;
        }
    }
    __syncthreads();
    if (tid < TM) {
        float s = red[0][tid] + red[1][tid] + red[2][tid] + red[3][tid];
        g_partS[(size_t)blockIdx.y * N2 + i0 + tid] = s;
    }
}

// ---------------------------------------------------------------------------
// Kernel 3a: per-row lse - pos.
// ---------------------------------------------------------------------------
__global__ void __launch_bounds__(128) rowfin_kernel() {
    int row = blockIdx.x * 128 + threadIdx.x;
    float s = 0.0f;
    #pragma unroll 8
    for (int t = 0; t < NJT; t++) s += g_partS[(size_t)t * N2 + row];
    g_lsep[row] = logf(s) - g_pos[row];
}

// ---------------------------------------------------------------------------
// Kernel 3b: mean over 8192 rows.
// ---------------------------------------------------------------------------
__global__ void __launch_bounds__(1024) mean_kernel(float* __restrict__ out) {
    const int t = threadIdx.x;
    float local = 0.0f;
    #pragma unroll
    for (int i = t; i < N2; i += 1024) local += g_lsep[i];
    #pragma unroll
    for (int off = 16; off > 0; off >>= 1)
        local += __shfl_xor_sync(0xffffffffu, local, off);
    __shared__ float ws[32];
    if ((t & 31) == 0) ws[t >> 5] = local;
    __syncthreads();
    if (t < 32) {
        float v = ws[t];
        #pragma unroll
        for (int off = 16; off > 0; off >>= 1)
            v += __shfl_xor_sync(0xffffffffu, v, off);
        if (t == 0) out[0] = v / (float)N2;
    }
}

// ---------------------------------------------------------------------------
extern "C" void kernel_launch(void* const* d_in, const int* in_sizes, int n_in,
                              void* d_out, int out_size) {
    const float* z = (const float*)d_in[0];
    cudaFuncSetAttribute(sim_kernel, cudaFuncAttributeMaxDynamicSharedMemorySize,
                         SMEM_BYTES);
    normalize_kernel<<<N2, 128>>>(z);
    dim3 grid(N2 / TM, N2 / TN);
    sim_kernel<<<grid, 256, SMEM_BYTES>>>();
    rowfin_kernel<<<N2 / 128, 128>>>();
    mean_kernel<<<1, 1024>>>((float*)d_out);
}

// round 8
// speedup vs baseline: 1.7162x; 1.7162x over previous
#include <cuda_runtime.h>
#include <cuda_bf16.h>
#include <cstdint>
#include <math.h>

// Problem constants
#define N2     8192     // 2N rows
#define HALF_N 4096     // pos index = i ^ HALF_N
#define D      512      // feature dim
#define SCALE  2.0f     // 1 / TEMPERATURE

// Tiling
#define TM     128
#define TN     128
#define KC     64       // bf16 per k-chunk (128 bytes/row)
#define NCHUNK (D / KC) // 8
#define NT     (N2 / TN)                   // 64 tile rows/cols
#define NTRI   (NT * (NT + 1) / 2)         // 2080 upper-tri tiles
#define STAGE_BYTES (TM * KC * 2 * 2)      // A+B one stage = 32 KB
#define SMEM_BYTES  (2 * STAGE_BYTES)      // 2 stages = 64 KB

// Device scratch (static: allocation-free per harness rules)
__device__ __nv_bfloat16 g_zb[N2 * D];   // normalized rows, bf16 (8 MB)
__device__ float g_partS[NT * N2];       // row   sums: written by CTA (I,J) at [J][rows of I]
__device__ float g_partC[NT * N2];       // col   sums: written by CTA (I,J) at [I][rows of J]
__device__ float g_pos[N2];              // positive logit per row
__device__ float g_lsep[N2];             // lse - pos per row

// ---------------------------------------------------------------------------
// PTX helpers
// ---------------------------------------------------------------------------
__device__ __forceinline__ uint32_t smem_u32(const void* p) {
    uint32_t a;
    asm("{ .reg .u64 t; cvta.to.shared.u64 t, %1; cvt.u32.u64 %0, t; }"
        : "=r"(a) : "l"(p));
    return a;
}
__device__ __forceinline__ void cp_async16(uint32_t dst, const void* src) {
    asm volatile("cp.async.cg.shared.global [%0], [%1], 16;"
                 :: "r"(dst), "l"(src) : "memory");
}
__device__ __forceinline__ void cp_commit() {
    asm volatile("cp.async.commit_group;" ::: "memory");
}
template <int N>
__device__ __forceinline__ void cp_wait() {
    asm volatile("cp.async.wait_group %0;" :: "n"(N) : "memory");
}
__device__ __forceinline__ void ldm_x4(uint32_t& r0, uint32_t& r1, uint32_t& r2,
                                       uint32_t& r3, uint32_t addr) {
    asm volatile("ldmatrix.sync.aligned.m8n8.x4.shared.b16 {%0,%1,%2,%3}, [%4];"
                 : "=r"(r0), "=r"(r1), "=r"(r2), "=r"(r3) : "r"(addr));
}
__device__ __forceinline__ void mma16816(float* d, const uint32_t* a,
                                         uint32_t b0, uint32_t b1) {
    asm volatile(
        "mma.sync.aligned.m16n8k16.row.col.f32.bf16.bf16.f32 "
        "{%0,%1,%2,%3}, {%4,%5,%6,%7}, {%8,%9}, {%0,%1,%2,%3};"
        : "+f"(d[0]), "+f"(d[1]), "+f"(d[2]), "+f"(d[3])
        : "r"(a[0]), "r"(a[1]), "r"(a[2]), "r"(a[3]), "r"(b0), "r"(b1));
}

// swizzled byte offset inside a 128x64-bf16 tile (128 B rows, 16 B units)
__device__ __forceinline__ uint32_t sw_off(int row, int unit) {
    return (uint32_t)(row * 128 + ((unit ^ (row & 7)) << 4));
}

// ---------------------------------------------------------------------------
// Kernel 1: row L2-normalize + bf16 convert. One block (128 thr) per row.
// ---------------------------------------------------------------------------
__global__ void __launch_bounds__(128) normalize_kernel(const float* __restrict__ z) {
    int row = blockIdx.x;
    int t   = threadIdx.x;
    float4 v = ((const float4*)(z + (size_t)row * D))[t];
    float ss = v.x * v.x + v.y * v.y + v.z * v.z + v.w * v.w;
    #pragma unroll
    for (int off = 16; off > 0; off >>= 1)
        ss += __shfl_xor_sync(0xffffffffu, ss, off);
    __shared__ float ws[4];
    if ((t & 31) == 0) ws[t >> 5] = ss;
    __syncthreads();
    float inv = 1.0f / fmaxf(sqrtf(ws[0] + ws[1] + ws[2] + ws[3]), 1e-12f);
    __nv_bfloat162 p0 = __floats2bfloat162_rn(v.x * inv, v.y * inv);
    __nv_bfloat162 p1 = __floats2bfloat162_rn(v.z * inv, v.w * inv);
    uint2 o;
    o.x = *(const uint32_t*)&p0;
    o.y = *(const uint32_t*)&p1;
    ((uint2*)(g_zb + (size_t)row * D))[t] = o;
}

// ---------------------------------------------------------------------------
// Kernel 2: upper-triangular 128x128 sim tiles (symmetry: sim = sim^T).
// Grid NTRI linear; CTA decodes (I, J) with I <= J. 256 threads = 8 warps.
// Row sums -> partS[J][rows of I]; col sums (I<J) -> partC[I][rows of J].
// ---------------------------------------------------------------------------
__global__ void __launch_bounds__(256, 2) sim_kernel() {
    extern __shared__ __align__(128) char smem[];
    __shared__ float red[4][TM];         // cross-warp (wn) row-sum reduction
    __shared__ float redc[8][32];        // per-warp col-sum partials

    // decode linear bid -> (I, J), I <= J
    int bid = blockIdx.x, I = 0, rem = NT;
    while (bid >= rem) { bid -= rem; I++; rem--; }
    const int J = I + bid;

    const int tid = threadIdx.x;
    const int wid = tid >> 5;
    const int lid = tid & 31;
    const int wm  = wid & 1;             // 0..1 -> 64 rows
    const int wn  = wid >> 1;            // 0..3 -> 32 cols
    const int i0  = I * TM;
    const int j0  = J * TN;

    const uint32_t sA0 = smem_u32(smem);
    auto a_base = [&](int s) { return sA0 + (uint32_t)s * STAGE_BYTES; };
    auto b_base = [&](int s) { return sA0 + (uint32_t)s * STAGE_BYTES + TM * KC * 2; };

    auto load_chunk = [&](int c, int s) {
        const uint32_t ab = a_base(s), bb = b_base(s);
        #pragma unroll
        for (int u = 0; u < 4; u++) {                    // 1024 units / 256 thr
            int unit = tid + u * 256;
            int r = unit >> 3, b = unit & 7;
            uint32_t off = sw_off(r, b);
            const __nv_bfloat16* src_a = g_zb + (size_t)(i0 + r) * D + c * KC + b * 8;
            const __nv_bfloat16* src_b = g_zb + (size_t)(j0 + r) * D + c * KC + b * 8;
            cp_async16(ab + off, src_a);
            cp_async16(bb + off, src_b);
        }
        cp_commit();
    };

    float acc[4][4][4];
    #pragma unroll
    for (int mm = 0; mm < 4; mm++)
        #pragma unroll
        for (int nn = 0; nn < 4; nn++)
            #pragma unroll
            for (int e = 0; e < 4; e++) acc[mm][nn][e] = 0.0f;

    load_chunk(0, 0);

    for (int c = 0; c < NCHUNK; c++) {
        if (c + 1 < NCHUNK) {
            load_chunk(c + 1, (c + 1) & 1);
            cp_wait<1>();
        } else {
            cp_wait<0>();
        }
        __syncthreads();

        const uint32_t ab = a_base(c & 1), bb = b_base(c & 1);
        const int tile_id = lid >> 3, rowin = lid & 7;

        #pragma unroll
        for (int ks = 0; ks < 4; ks++) {                 // k0 = ks*16
            const int cu = ks * 2 + (tile_id >> 1);
            uint32_t a[4][4], bfr[2][4];
            #pragma unroll
            for (int mm = 0; mm < 4; mm++) {
                int m = wm * 64 + mm * 16 + rowin + (tile_id & 1) * 8;
                ldm_x4(a[mm][0], a[mm][1], a[mm][2], a[mm][3],
                       ab + sw_off(m, cu));
            }
            #pragma unroll
            for (int nb = 0; nb < 2; nb++) {
                int n = wn * 32 + nb * 16 + rowin + (tile_id & 1) * 8;
                ldm_x4(bfr[nb][0], bfr[nb][1], bfr[nb][2], bfr[nb][3],
                       bb + sw_off(n, cu));
            }
            #pragma unroll
            for (int mm = 0; mm < 4; mm++) {
                #pragma unroll
                for (int nn = 0; nn < 4; nn++) {
                    int nb = nn >> 1, odd = nn & 1;
                    mma16816(acc[mm][nn], a[mm],
                             bfr[nb][odd], bfr[nb][2 + odd]);
                }
            }
        }
        __syncthreads();
    }

    // ---- Epilogue ----
    // D-frag layout: lane holds rows {gq, gq+8} (gq = lid>>2), cols qi*2, qi*2+1.
    const int gq = lid >> 2;
    const int qi = lid & 3;
    float colp[4][2];
    #pragma unroll
    for (int nn = 0; nn < 4; nn++) { colp[nn][0] = 0.0f; colp[nn][1] = 0.0f; }

    #pragma unroll
    for (int mm = 0; mm < 4; mm++) {
        float rs0 = 0.0f, rs1 = 0.0f;
        const int gi0 = i0 + wm * 64 + mm * 16 + gq;
        const int gi1 = gi0 + 8;
        const int p0  = gi0 ^ HALF_N;
        const int p1  = gi1 ^ HALF_N;
        #pragma unroll
        for (int nn = 0; nn < 4; nn++) {
            const int j = j0 + wn * 32 + nn * 8 + qi * 2;
            float l00 = SCALE * acc[mm][nn][0];
            float l01 = SCALE * acc[mm][nn][1];
            float l10 = SCALE * acc[mm][nn][2];
            float l11 = SCALE * acc[mm][nn][3];
            // positive capture: entry (i, i^N) exists in exactly one upper-tri
            // tile; write both g_pos[i] and g_pos[i^N] (symmetric value).
            if (j     == p0) { g_pos[gi0] = l00; g_pos[j]     = l00; }
            if (j + 1 == p0) { g_pos[gi0] = l01; g_pos[j + 1] = l01; }
            if (j     == p1) { g_pos[gi1] = l10; g_pos[j]     = l10; }
            if (j + 1 == p1) { g_pos[gi1] = l11; g_pos[j + 1] = l11; }
            float e00 = (j     != gi0) ? __expf(l00) : 0.0f;
            float e01 = (j + 1 != gi0) ? __expf(l01) : 0.0f;
            float e10 = (j     != gi1) ? __expf(l10) : 0.0f;
            float e11 = (j + 1 != gi1) ? __expf(l11) : 0.0f;
            rs0 += e00 + e01;
            rs1 += e10 + e11;
            colp[nn][0] += e00 + e10;
            colp[nn][1] += e01 + e11;
        }
        // row-sum reduce across the 4 qi lanes
        rs0 += __shfl_xor_sync(0xffffffffu, rs0, 1);
        rs0 += __shfl_xor_sync(0xffffffffu, rs0, 2);
        rs1 += __shfl_xor_sync(0xffffffffu, rs1, 1);
        rs1 += __shfl_xor_sync(0xffffffffu, rs1, 2);
        if (qi == 0) {
            red[wn][wm * 64 + mm * 16 + gq]     = rs0;
            red[wn][wm * 64 + mm * 16 + gq + 8] = rs1;
        }
    }

    // col-sum reduce across gq lanes (bits 2..4 of lid), per warp
    if (I != J) {
        #pragma unroll
        for (int nn = 0; nn < 4; nn++) {
            #pragma unroll
            for (int e = 0; e < 2; e++) {
                float v = colp[nn][e];
                v += __shfl_xor_sync(0xffffffffu, v, 4);
                v += __shfl_xor_sync(0xffffffffu, v, 8);
                v += __shfl_xor_sync(0xffffffffu, v, 16);
                if (gq == 0) redc[wid][nn * 8 + qi * 2 + e] = v;
            }
        }
    }
    __syncthreads();

    if (tid < TM) {
        float s = red[0][tid] + red[1][tid] + red[2][tid] + red[3][tid];
        g_partS[(size_t)J * N2 + i0 + tid] = s;
        if (I != J) {
            int wnc = tid >> 5, cin = tid & 31;
            float cs = redc[2 * wnc][cin] + redc[2 * wnc + 1][cin];
            g_partC[(size_t)I * N2 + j0 + tid] = cs;
        }
    }
}

// ---------------------------------------------------------------------------
// Kernel 3a: per-row lse - pos.  Block = one 128-row tile (uniform loops).
// ---------------------------------------------------------------------------
__global__ void __launch_bounds__(128) rowfin_kernel() {
    const int Ir  = blockIdx.x;
    const int row = Ir * 128 + threadIdx.x;
    float s = 0.0f;
    for (int Jt = Ir; Jt < NT; Jt++)   s += g_partS[(size_t)Jt * N2 + row];
    for (int Ip = 0; Ip < Ir;  Ip++)   s += g_partC[(size_t)Ip * N2 + row];
    g_lsep[row] = logf(s) - g_pos[row];
}

// ---------------------------------------------------------------------------
// Kernel 3b: mean over 8192 rows.
// ---------------------------------------------------------------------------
__global__ void __launch_bounds__(1024) mean_kernel(float* __restrict__ out) {
    const int t = threadIdx.x;
    float local = 0.0f;
    #pragma unroll
    for (int i = t; i < N2; i += 1024) local += g_lsep[i];
    #pragma unroll
    for (int off = 16; off > 0; off >>= 1)
        local += __shfl_xor_sync(0xffffffffu, local, off);
    __shared__ float ws[32];
    if ((t & 31) == 0) ws[t >> 5] = local;
    __syncthreads();
    if (t < 32) {
        float v = ws[t];
        #pragma unroll
        for (int off = 16; off > 0; off >>= 1)
            v += __shfl_xor_sync(0xffffffffu, v, off);
        if (t == 0) out[0] = v / (float)N2;
    }
}

// ---------------------------------------------------------------------------
extern "C" void kernel_launch(void* const* d_in, const int* in_sizes, int n_in,
                              void* d_out, int out_size) {
    const float* z = (const float*)d_in[0];
    cudaFuncSetAttribute(sim_kernel, cudaFuncAttributeMaxDynamicSharedMemorySize,
                         SMEM_BYTES);
    normalize_kernel<<<N2, 128>>>(z);
    sim_kernel<<<NTRI, 256, SMEM_BYTES>>>();
    rowfin_kernel<<<NT, 128>>>();
    mean_kernel<<<1, 1024>>>((float*)d_out);
}